// round 13
// baseline (speedup 1.0000x reference)
#include <cuda_runtime.h>
#include <cuda_fp16.h>
#include <mma.h>
#include <math.h>

using namespace nvcuda;

#define NN   100000
#define EE   500000
#define TT   8
#define MSGD 64
#define HIDD 64
#define CC   16

typedef unsigned long long ull;

// ---------------------------------------------------------------------------
// Device scratch
// ---------------------------------------------------------------------------
__device__ __align__(16) float g_reduced[(size_t)NN * MSGD];
__device__ __align__(32) __half g_Wh[256 * 128];   // packed fp16 GRU weights
__device__ int g_counts[TT];
__device__ int g_cursor[TT];
__device__ int g_src_s[EE];
__device__ int g_dst_s[EE];

// ---------------------------------------------------------------------------
// Packed fp32x2 helpers (Blackwell FFMA2)
// ---------------------------------------------------------------------------
__device__ __forceinline__ void fma2(ull& d, ull a, ull b) {
    asm volatile("fma.rn.f32x2 %0, %1, %2, %0;" : "+l"(d) : "l"(a), "l"(b));
}
__device__ __forceinline__ float2 asf2(ull v) {
    float2 r;
    asm("mov.b64 {%0, %1}, %2;" : "=f"(r.x), "=f"(r.y) : "l"(v));
    return r;
}
__device__ __forceinline__ float fast_sigmoid(float x) {
    return __fdividef(1.f, 1.f + __expf(-x));
}
__device__ __forceinline__ float fast_tanh(float x) {
    return 1.f - __fdividef(2.f, __expf(2.f * x) + 1.f);
}

// ---------------------------------------------------------------------------
// Kernel 0: zero reduction buffer + reset counters
// ---------------------------------------------------------------------------
__global__ void zero_kernel() {
    int i = blockIdx.x * blockDim.x + threadIdx.x;
    if (i < NN * MSGD / 4) {
        reinterpret_cast<float4*>(g_reduced)[i] = make_float4(0.f, 0.f, 0.f, 0.f);
    }
    if (blockIdx.x == 0 && threadIdx.x < TT) {
        g_counts[threadIdx.x] = 0;
        g_cursor[threadIdx.x] = 0;
    }
}

// ---------------------------------------------------------------------------
// Kernel 0b: pack GRU weights to fp16 ONCE.
//   g in [0,64):    [W_ih[g] | W_hh[g]]        (r)
//   g in [64,128):  [W_ih[g] | W_hh[g]]        (z)
//   g in [128,192): [W_ih[g] | 0      ]        (i_n, W_ih row g = 128+j)
//   g in [192,256): [0       | W_hh[g-64]]     (h_n, W_hh row g-64 = 128+j)
// ---------------------------------------------------------------------------
__global__ void wprep_kernel(const float* __restrict__ W_ih,
                             const float* __restrict__ W_hh) {
    int idx = blockIdx.x * blockDim.x + threadIdx.x;
    if (idx >= 256 * 128) return;
    int g = idx >> 7, k = idx & 127;
    float w;
    if (g < 128) {
        w = (k < 64) ? W_ih[g * 64 + k] : W_hh[g * 64 + (k - 64)];
    } else if (g < 192) {
        w = (k < 64) ? W_ih[g * 64 + k] : 0.f;
    } else {
        w = (k < 64) ? 0.f : W_hh[(g - 64) * 64 + (k - 64)];
    }
    g_Wh[idx] = __float2half_rn(w);
}

// ---------------------------------------------------------------------------
// Kernel 1: per-block histogram of edge types
// ---------------------------------------------------------------------------
__global__ void hist_kernel(const int* __restrict__ etype) {
    __shared__ int h[TT];
    if (threadIdx.x < TT) h[threadIdx.x] = 0;
    __syncthreads();
    int e = blockIdx.x * blockDim.x + threadIdx.x;
    if (e < EE) atomicAdd(&h[etype[e]], 1);
    __syncthreads();
    if (threadIdx.x < TT) atomicAdd(&g_counts[threadIdx.x], h[threadIdx.x]);
}

// ---------------------------------------------------------------------------
// Kernel 2: bin edges by type
// ---------------------------------------------------------------------------
__global__ void scatter_kernel(const int* __restrict__ etype,
                               const int* __restrict__ src,
                               const int* __restrict__ dst) {
    __shared__ int h[TT], base[TT], h2[TT];
    int e = blockIdx.x * blockDim.x + threadIdx.x;
    if (threadIdx.x < TT) { h[threadIdx.x] = 0; h2[threadIdx.x] = 0; }
    __syncthreads();
    int t = 0, s = 0, d = 0;
    bool valid = (e < EE);
    if (valid) {
        t = etype[e]; s = src[e]; d = dst[e];
        atomicAdd(&h[t], 1);
    }
    __syncthreads();
    if (threadIdx.x < TT) {
        int b = 0;
#pragma unroll
        for (int q = 0; q < TT; q++) {
            int c = g_counts[q];
            if (q < (int)threadIdx.x) b += c;
        }
        base[threadIdx.x] = b + atomicAdd(&g_cursor[threadIdx.x], h[threadIdx.x]);
    }
    __syncthreads();
    if (valid) {
        int pos = base[t] + atomicAdd(&h2[t], 1);
        g_src_s[pos] = s;
        g_dst_s[pos] = d;
    }
}

// ---------------------------------------------------------------------------
// Kernel 3: edge messages — EXACT R4 WINNER (142 us measured 5x).
// ---------------------------------------------------------------------------
#define EBLOCKS 148
#define ETHREADS 256
#define NWARP   (EBLOCKS * ETHREADS / 32)              // 1184
#define CHUNK   ((EE + NWARP - 1) / NWARP)             // 423

__global__ void __launch_bounds__(ETHREADS, 1)
edge_kernel(const float* __restrict__ features,
            const float* __restrict__ edge_emb) {
    __shared__ float4 sf[ETHREADS / 32][8][16];
    const unsigned FULL = 0xffffffffu;
    const int wib = threadIdx.x >> 5, lane = threadIdx.x & 31;

    int w = blockIdx.x * (ETHREADS / 32) + wib;
    long e0 = (long)w * CHUNK;
    if (e0 >= EE) return;
    long e1 = e0 + CHUNK;
    if (e1 > EE) e1 = EE;

    int bases[TT + 1];
    {
        int b = 0;
#pragma unroll
        for (int t = 0; t < TT; t++) { bases[t] = b; b += g_counts[t]; }
        bases[TT] = b;
    }

    ull wA[32], wB[32];
    long e = e0;
    int t = 0;
    while (e < e1) {
        while (bases[t + 1] <= e) t++;
        long seg_end = bases[t + 1] < e1 ? bases[t + 1] : e1;

        {
            const ulonglong2* pA = reinterpret_cast<const ulonglong2*>(
                edge_emb + (size_t)t * 4096 + (size_t)(2 * lane) * 64);
            const ulonglong2* pB = reinterpret_cast<const ulonglong2*>(
                edge_emb + (size_t)t * 4096 + (size_t)(2 * lane + 1) * 64);
#pragma unroll
            for (int q = 0; q < 16; q++) {
                ulonglong2 a = pA[q]; wA[2 * q] = a.x; wA[2 * q + 1] = a.y;
            }
#pragma unroll
            for (int q = 0; q < 16; q++) {
                ulonglong2 b = pB[q]; wB[2 * q] = b.x; wB[2 * q + 1] = b.y;
            }
        }

        for (long b0 = e; b0 < seg_end; b0 += 32) {
            int nb = (int)((seg_end - b0 < 32) ? (seg_end - b0) : 32);
            int my_s = 0, my_d = 0;
            if (lane < nb) {
                my_s = g_src_s[b0 + lane];
                my_d = g_dst_s[b0 + lane];
            }
#pragma unroll
            for (int j = 0; j < 6; j++) {
                if (j < nb) {
                    int s = __shfl_sync(FULL, my_s, j);
                    if (lane < 16) {
                        unsigned sp = (unsigned)__cvta_generic_to_shared(
                            &sf[wib][j & 7][lane]);
                        asm volatile("cp.async.cg.shared.global [%0], [%1], 16;"
                                     :: "r"(sp),
                                        "l"(features + (size_t)s * 64 + lane * 4));
                    }
                }
                asm volatile("cp.async.commit_group;");
            }
            for (int j = 0; j < nb; j++) {
                asm volatile("cp.async.wait_group 5;");
                __syncwarp();
                if (j + 6 < nb) {
                    int s = __shfl_sync(FULL, my_s, j + 6);
                    if (lane < 16) {
                        unsigned sp = (unsigned)__cvta_generic_to_shared(
                            &sf[wib][(j + 6) & 7][lane]);
                        asm volatile("cp.async.cg.shared.global [%0], [%1], 16;"
                                     :: "r"(sp),
                                        "l"(features + (size_t)s * 64 + lane * 4));
                    }
                }
                asm volatile("cp.async.commit_group;");

                int d = __shfl_sync(FULL, my_d, j);
                const ulonglong2* fp = reinterpret_cast<const ulonglong2*>(
                    &sf[wib][j & 7][0]);
                ull a0 = 0, a1 = 0, c0 = 0, c1 = 0;
#pragma unroll
                for (int q = 0; q < 16; q += 2) {
                    ulonglong2 f0 = fp[q], f1 = fp[q + 1];
                    fma2(a0, wA[2 * q],     f0.x); fma2(a0, wA[2 * q + 1], f0.y);
                    fma2(c0, wB[2 * q],     f0.x); fma2(c0, wB[2 * q + 1], f0.y);
                    fma2(a1, wA[2 * q + 2], f1.x); fma2(a1, wA[2 * q + 3], f1.y);
                    fma2(c1, wB[2 * q + 2], f1.x); fma2(c1, wB[2 * q + 3], f1.y);
                }
                float2 fa0 = asf2(a0), fa1 = asf2(a1);
                float2 fc0 = asf2(c0), fc1 = asf2(c1);
                float r0 = (fa0.x + fa0.y) + (fa1.x + fa1.y);
                float r1 = (fc0.x + fc0.y) + (fc1.x + fc1.y);
                float p0 = __shfl_xor_sync(FULL, r0, 1);
                float p1 = __shfl_xor_sync(FULL, r1, 1);
                if (!(lane & 1)) {
                    const float* op = g_reduced + (size_t)d * 64 + 2 * lane;
                    asm volatile("red.global.add.v4.f32 [%0], {%1, %2, %3, %4};"
                                 :: "l"(op), "f"(r0), "f"(r1), "f"(p0), "f"(p1)
                                 : "memory");
                }
            }
            asm volatile("cp.async.wait_group 0;");
            __syncwarp();
        }
        e = seg_end;
    }
}

// ---------------------------------------------------------------------------
// Kernel 4: GRU via tensor cores. 512 threads (16 warps), 1 CTA/SM,
// 4 acc fragments/warp (32 regs -> no spill), W' staged to smem once/block.
// ---------------------------------------------------------------------------
#define MTILE 64
#define GSTR  72                              // gates smem stride (floats)
#define GTHREADS 512
#define NGB ((NN + MTILE - 1) / MTILE)        // 1563
// smem: gates f32 [256][GSTR] = 73728B @0, Xh half [64][136] = 17408B @73728,
//       Wh half [256][128] = 65536B @91136 -> total 156672B
#define GEMM_SMEM 156672

__global__ void __launch_bounds__(GTHREADS, 1)
gru_gemm_kernel(const float* __restrict__ features,
                const float* __restrict__ b_ih, const float* __restrict__ b_hh,
                const float* __restrict__ W_out, const float* __restrict__ b_out,
                float* __restrict__ out) {
    extern __shared__ char smem[];
    float*  gates_s = (float*)smem;                    // [256][GSTR]
    __half* Xh      = (__half*)(smem + 73728);         // [64][136]
    __half* Wh      = (__half*)(smem + 91136);         // [256][128]

    int tid  = threadIdx.x;
    int base = blockIdx.x * MTILE;

    // ---- W' global(fp16, warm L1) -> smem: 4096 int4, 8 per thread ----
    {
        const int4* src = reinterpret_cast<const int4*>(g_Wh);
        int4* dst = reinterpret_cast<int4*>(Wh);
        for (int i = tid; i < 4096; i += GTHREADS) dst[i] = src[i];
    }
    // ---- X tile: [reduced | features] -> fp16 smem (zero-fill past NN) ----
    for (int idx = tid; idx < MTILE * 32; idx += GTHREADS) {
        int r = idx >> 5, q = idx & 31;
        int n = base + r;
        float4 v = make_float4(0.f, 0.f, 0.f, 0.f);
        if (n < NN) {
            v = (q < 16)
                ? reinterpret_cast<const float4*>(g_reduced + (size_t)n * 64)[q]
                : reinterpret_cast<const float4*>(features + (size_t)n * 64)[q - 16];
        }
        __half2* dst = reinterpret_cast<__half2*>(Xh + r * 136 + q * 4);
        dst[0] = __floats2half2_rn(v.x, v.y);
        dst[1] = __floats2half2_rn(v.z, v.w);
    }
    __syncthreads();

    // ---- GEMM: 16 warps; warp = 16 node-rows x 64 gate-cols (4 fragments) ----
    {
        int wid = tid >> 5;
        int wm = wid & 3;        // node rows wm*16
        int wn = wid >> 2;       // gates [wn*64, wn*64+64)
        wmma::fragment<wmma::accumulator, 16, 16, 16, float> acc[4];
#pragma unroll
        for (int j = 0; j < 4; j++) wmma::fill_fragment(acc[j], 0.f);

#pragma unroll 1
        for (int ks = 0; ks < 8; ks++) {
            wmma::fragment<wmma::matrix_a, 16, 16, 16, __half, wmma::row_major> a;
            wmma::load_matrix_sync(a, Xh + (wm * 16) * 136 + ks * 16, 136);
#pragma unroll
            for (int nt = 0; nt < 4; nt++) {
                wmma::fragment<wmma::matrix_b, 16, 16, 16, __half, wmma::col_major> b;
                wmma::load_matrix_sync(b, Wh + (size_t)(wn * 64 + nt * 16) * 128 + ks * 16, 128);
                wmma::mma_sync(acc[nt], a, b, acc[nt]);
            }
        }
#pragma unroll
        for (int nt = 0; nt < 4; nt++) {
            wmma::store_matrix_sync(gates_s + (size_t)(wn * 64 + nt * 16) * GSTR + wm * 16,
                                    acc[nt], GSTR, wmma::mem_col_major);
        }
    }
    __syncthreads();

    // ---- epilogue constants overlay the Xh region (GEMM done with Xh) ----
    float* sWoT  = (float*)Xh;        // [64][16]
    float* sb_r  = sWoT + 1024;       // 64
    float* sb_z  = sb_r + 64;         // 64
    float* sb_in = sb_z + 64;         // 64
    float* sb_hn = sb_in + 64;        // 64
    float* sbout = sb_hn + 64;        // 16
    for (int i = tid; i < 1024; i += GTHREADS) {
        int j = i >> 4, c = i & 15;
        sWoT[j * 16 + c] = W_out[c * 64 + j];
    }
    if (tid < 64) {
        sb_r[tid]  = b_ih[tid] + b_hh[tid];
        sb_z[tid]  = b_ih[64 + tid] + b_hh[64 + tid];
        sb_in[tid] = b_ih[128 + tid];
        sb_hn[tid] = b_hh[128 + tid];
    }
    if (tid >= 64 && tid < 80) sbout[tid - 64] = b_out[tid - 64];
    __syncthreads();

    // ---- epilogue: 8 threads per node, each owns 8 of 64 j's ----
    {
        int node = tid >> 3, part = tid & 7;
        int n = base + node;
        float oacc[16];
#pragma unroll
        for (int c = 0; c < 16; c++) oacc[c] = 0.f;

        if (n < NN) {
            const float4* hp = reinterpret_cast<const float4*>(features + (size_t)n * 64);
#pragma unroll
            for (int dq = 0; dq < 2; dq++) {
                int jq = part * 2 + dq;
                float4 hv = hp[jq];
#pragma unroll
                for (int dj = 0; dj < 4; dj++) {
                    int j = jq * 4 + dj;
                    float rv  = gates_s[(size_t)(j      ) * GSTR + node] + sb_r[j];
                    float zv  = gates_s[(size_t)(64  + j) * GSTR + node] + sb_z[j];
                    float inv = gates_s[(size_t)(128 + j) * GSTR + node] + sb_in[j];
                    float hnv = gates_s[(size_t)(192 + j) * GSTR + node] + sb_hn[j];
                    float r  = fast_sigmoid(rv);
                    float z  = fast_sigmoid(zv);
                    float ng = fast_tanh(inv + r * hnv);
                    float hj = (dj == 0) ? hv.x : (dj == 1) ? hv.y : (dj == 2) ? hv.z : hv.w;
                    float hnew = (1.f - z) * ng + z * hj;
                    const float* wo = sWoT + j * 16;
#pragma unroll
                    for (int c = 0; c < 16; c++) oacc[c] += wo[c] * hnew;
                }
            }
        }
        // combine 8 parts (lanes node*8..node*8+7 sit in one warp)
#pragma unroll
        for (int c = 0; c < 16; c++) {
            oacc[c] += __shfl_xor_sync(0xffffffffu, oacc[c], 1);
            oacc[c] += __shfl_xor_sync(0xffffffffu, oacc[c], 2);
            oacc[c] += __shfl_xor_sync(0xffffffffu, oacc[c], 4);
        }
        if (part == 0 && n < NN) {
            float4* op = reinterpret_cast<float4*>(out + (size_t)n * 16);
#pragma unroll
            for (int q = 0; q < 4; q++)
                op[q] = make_float4(oacc[4 * q] + sbout[4 * q],
                                    oacc[4 * q + 1] + sbout[4 * q + 1],
                                    oacc[4 * q + 2] + sbout[4 * q + 2],
                                    oacc[4 * q + 3] + sbout[4 * q + 3]);
        }
    }
}

// ---------------------------------------------------------------------------
extern "C" void kernel_launch(void* const* d_in, const int* in_sizes, int n_in,
                              void* d_out, int out_size) {
    const float* features = (const float*)d_in[0];
    const float* edge_emb = (const float*)d_in[1];
    const float* W_ih     = (const float*)d_in[2];
    const float* W_hh     = (const float*)d_in[3];
    const float* b_ih     = (const float*)d_in[4];
    const float* b_hh     = (const float*)d_in[5];
    const float* W_out    = (const float*)d_in[6];
    const float* b_out    = (const float*)d_in[7];
    const int*   etype    = (const int*)d_in[8];
    const int*   src      = (const int*)d_in[9];
    const int*   dst      = (const int*)d_in[10];
    float*       out      = (float*)d_out;

    cudaFuncSetAttribute(gru_gemm_kernel,
                         cudaFuncAttributeMaxDynamicSharedMemorySize, GEMM_SMEM);

    zero_kernel<<<(NN * MSGD / 4 + 255) / 256, 256>>>();
    wprep_kernel<<<128, 256>>>(W_ih, W_hh);
    hist_kernel<<<(EE + 511) / 512, 512>>>(etype);
    scatter_kernel<<<(EE + 511) / 512, 512>>>(etype, src, dst);
    edge_kernel<<<EBLOCKS, ETHREADS>>>(features, edge_emb);
    gru_gemm_kernel<<<NGB, GTHREADS, GEMM_SMEM>>>(features, b_ih, b_hh,
                                                  W_out, b_out, out);
}

// round 14
// speedup vs baseline: 1.2770x; 1.2770x over previous
#include <cuda_runtime.h>
#include <cuda_fp16.h>
#include <mma.h>
#include <math.h>

using namespace nvcuda;

#define NN   100000
#define EE   500000
#define TT   8
#define MSGD 64
#define HIDD 64
#define CC   16

typedef unsigned long long ull;

// ---------------------------------------------------------------------------
// Device scratch
// ---------------------------------------------------------------------------
__device__ __align__(16) float g_reduced[(size_t)NN * MSGD];
__device__ __align__(32) __half g_edge_h[TT * 64 * 64];   // fp16 edge matrices
__device__ int g_counts[TT];
__device__ int g_cursor[TT];
__device__ int g_src_s[EE];
__device__ int g_dst_s[EE];

// ---------------------------------------------------------------------------
// Packed fp32x2 helpers (Blackwell FFMA2)
// ---------------------------------------------------------------------------
__device__ __forceinline__ void fma2(ull& d, ull a, ull b) {
    asm volatile("fma.rn.f32x2 %0, %1, %2, %0;" : "+l"(d) : "l"(a), "l"(b));
}
__device__ __forceinline__ float2 asf2(ull v) {
    float2 r;
    asm("mov.b64 {%0, %1}, %2;" : "=f"(r.x), "=f"(r.y) : "l"(v));
    return r;
}
__device__ __forceinline__ float fast_sigmoid(float x) {
    return __fdividef(1.f, 1.f + __expf(-x));
}
__device__ __forceinline__ float fast_tanh(float x) {
    return 1.f - __fdividef(2.f, __expf(2.f * x) + 1.f);
}

// ---------------------------------------------------------------------------
// Kernel 0: zero reduction buffer + reset counters
// ---------------------------------------------------------------------------
__global__ void zero_kernel() {
    int i = blockIdx.x * blockDim.x + threadIdx.x;
    if (i < NN * MSGD / 4) {
        reinterpret_cast<float4*>(g_reduced)[i] = make_float4(0.f, 0.f, 0.f, 0.f);
    }
    if (blockIdx.x == 0 && threadIdx.x < TT) {
        g_counts[threadIdx.x] = 0;
        g_cursor[threadIdx.x] = 0;
    }
}

// ---------------------------------------------------------------------------
// Kernel 0b: edge matrices -> fp16 once (same [t][m][h] layout)
// ---------------------------------------------------------------------------
__global__ void wprep_edge_kernel(const float* __restrict__ edge_emb) {
    int i = blockIdx.x * blockDim.x + threadIdx.x;
    if (i < TT * 4096) g_edge_h[i] = __float2half_rn(edge_emb[i]);
}

// ---------------------------------------------------------------------------
// Kernel 1: per-block histogram of edge types
// ---------------------------------------------------------------------------
__global__ void hist_kernel(const int* __restrict__ etype) {
    __shared__ int h[TT];
    if (threadIdx.x < TT) h[threadIdx.x] = 0;
    __syncthreads();
    int e = blockIdx.x * blockDim.x + threadIdx.x;
    if (e < EE) atomicAdd(&h[etype[e]], 1);
    __syncthreads();
    if (threadIdx.x < TT) atomicAdd(&g_counts[threadIdx.x], h[threadIdx.x]);
}

// ---------------------------------------------------------------------------
// Kernel 2: bin edges by type
// ---------------------------------------------------------------------------
__global__ void scatter_kernel(const int* __restrict__ etype,
                               const int* __restrict__ src,
                               const int* __restrict__ dst) {
    __shared__ int h[TT], base[TT], h2[TT];
    int e = blockIdx.x * blockDim.x + threadIdx.x;
    if (threadIdx.x < TT) { h[threadIdx.x] = 0; h2[threadIdx.x] = 0; }
    __syncthreads();
    int t = 0, s = 0, d = 0;
    bool valid = (e < EE);
    if (valid) {
        t = etype[e]; s = src[e]; d = dst[e];
        atomicAdd(&h[t], 1);
    }
    __syncthreads();
    if (threadIdx.x < TT) {
        int b = 0;
#pragma unroll
        for (int q = 0; q < TT; q++) {
            int c = g_counts[q];
            if (q < (int)threadIdx.x) b += c;
        }
        base[threadIdx.x] = b + atomicAdd(&g_cursor[threadIdx.x], h[threadIdx.x]);
    }
    __syncthreads();
    if (valid) {
        int pos = base[t] + atomicAdd(&h2[t], 1);
        g_src_s[pos] = s;
        g_dst_s[pos] = d;
    }
}

// ---------------------------------------------------------------------------
// Kernel 3: edge messages via TENSOR CORES.
// Block = 64 sorted edges. Gather src features -> fp16 smem, then
// msgs[64,64] = X @ A_t^T with 8 warps (2 m16n16k16 acc frags each; B frags
// from global fp16 matrices, L1-warm). Scatter sub-segment rows with red.v4.
// Mixed-type tiles (<=7 of 7813) redo the GEMM per sub-segment.
// ---------------------------------------------------------------------------
#define EGB ((EE + 63) / 64)     // 7813
#define EGT 256

__global__ void __launch_bounds__(EGT)
edge_gemm_kernel(const float* __restrict__ features) {
    __shared__ __half Xh[64 * 72];     // [edge_row][h], ldm 72 (mult of 8)
    __shared__ float  msgs[64 * 68];   // [edge_row][m], ldm 68 (mult of 4)
    __shared__ int    sdst[64];

    long e0 = (long)blockIdx.x * 64;
    long e1 = e0 + 64;
    if (e1 > EE) e1 = EE;
    int tid = threadIdx.x;
    int r = tid >> 2, p = tid & 3;     // 4 threads per edge row

    int bases[TT + 1];
    {
        int b = 0;
#pragma unroll
        for (int t = 0; t < TT; t++) { bases[t] = b; b += g_counts[t]; }
        bases[TT] = b;
    }

    // ---- gather: row r <- features[src[e0+r]], fp16 convert ----
    {
        long e = e0 + r;
        __half2* dst = reinterpret_cast<__half2*>(Xh + r * 72 + p * 16);
        if (e < e1) {
            int s = g_src_s[e];
            if (p == 0) sdst[r] = g_dst_s[e];
            const float4* fp = reinterpret_cast<const float4*>(
                features + (size_t)s * 64 + p * 16);
            float4 v0 = fp[0], v1 = fp[1], v2 = fp[2], v3 = fp[3];
            dst[0] = __floats2half2_rn(v0.x, v0.y);
            dst[1] = __floats2half2_rn(v0.z, v0.w);
            dst[2] = __floats2half2_rn(v1.x, v1.y);
            dst[3] = __floats2half2_rn(v1.z, v1.w);
            dst[4] = __floats2half2_rn(v2.x, v2.y);
            dst[5] = __floats2half2_rn(v2.z, v2.w);
            dst[6] = __floats2half2_rn(v3.x, v3.y);
            dst[7] = __floats2half2_rn(v3.z, v3.w);
        } else {
            __half2 z = __floats2half2_rn(0.f, 0.f);
#pragma unroll
            for (int i = 0; i < 8; i++) dst[i] = z;
        }
    }
    __syncthreads();

    int wid = tid >> 5;
    int wm = wid & 3;      // rows [wm*16, wm*16+16)
    int wn = wid >> 2;     // cols [wn*32, wn*32+32)

    int t = 0;
    long s0 = e0;
    while (s0 < e1) {
        while (bases[t + 1] <= s0) t++;
        long send = (long)bases[t + 1] < e1 ? (long)bases[t + 1] : e1;

        // ---- GEMM with A_t over the whole tile ----
        {
            const __half* Bt = g_edge_h + (size_t)t * 4096;
            wmma::fragment<wmma::accumulator, 16, 16, 16, float> acc0, acc1;
            wmma::fill_fragment(acc0, 0.f);
            wmma::fill_fragment(acc1, 0.f);
#pragma unroll
            for (int k = 0; k < 4; k++) {
                wmma::fragment<wmma::matrix_a, 16, 16, 16, __half, wmma::row_major> a;
                wmma::load_matrix_sync(a, Xh + (wm * 16) * 72 + k * 16, 72);
                wmma::fragment<wmma::matrix_b, 16, 16, 16, __half, wmma::col_major> b0, b1;
                wmma::load_matrix_sync(b0, Bt + (wn * 32) * 64 + k * 16, 64);
                wmma::load_matrix_sync(b1, Bt + (wn * 32 + 16) * 64 + k * 16, 64);
                wmma::mma_sync(acc0, a, b0, acc0);
                wmma::mma_sync(acc1, a, b1, acc1);
            }
            wmma::store_matrix_sync(msgs + (wm * 16) * 68 + wn * 32, acc0, 68,
                                    wmma::mem_row_major);
            wmma::store_matrix_sync(msgs + (wm * 16) * 68 + wn * 32 + 16, acc1, 68,
                                    wmma::mem_row_major);
        }
        __syncthreads();

        // ---- scatter rows belonging to [s0, send) ----
        {
            long e = e0 + r;
            if (e >= s0 && e < send) {
                int d = sdst[r];
                float* op = g_reduced + (size_t)d * 64 + p * 16;
                const float* mp = msgs + r * 68 + p * 16;
#pragma unroll
                for (int i = 0; i < 4; i++) {
                    asm volatile("red.global.add.v4.f32 [%0], {%1, %2, %3, %4};"
                                 :: "l"(op + i * 4),
                                    "f"(mp[i * 4]), "f"(mp[i * 4 + 1]),
                                    "f"(mp[i * 4 + 2]), "f"(mp[i * 4 + 3])
                                 : "memory");
                }
            }
        }
        __syncthreads();   // msgs reuse safety for next sub-segment
        s0 = send;
    }
}

// ---------------------------------------------------------------------------
// Kernel 4: fused GRU + out projection — EXACT R5 node (measured ~166us).
// ---------------------------------------------------------------------------
#define NODE_SMEM (26000 * 4)
#define NBLOCKS 148
#define NTHREADS 256

__global__ void __launch_bounds__(NTHREADS, 1)
node_kernel(const float* __restrict__ features,
            const float* __restrict__ W_ih, const float* __restrict__ W_hh,
            const float* __restrict__ b_ih, const float* __restrict__ b_hh,
            const float* __restrict__ W_out, const float* __restrict__ b_out,
            float* __restrict__ out) {
    extern __shared__ float sm[];
    float* sWih  = sm;            // 12288
    float* sWhh  = sm + 12288;    // 12288
    float* sWoT  = sm + 24576;    // 1024 (W_out transposed [64][16])
    float* sbih  = sm + 25600;    // 192
    float* sbhh  = sm + 25792;    // 192
    float* sbout = sm + 25984;    // 16

    {
        float4* d1 = reinterpret_cast<float4*>(sWih);
        const float4* s1 = reinterpret_cast<const float4*>(W_ih);
        for (int i = threadIdx.x; i < 3072; i += blockDim.x) d1[i] = s1[i];
        float4* d2 = reinterpret_cast<float4*>(sWhh);
        const float4* s2 = reinterpret_cast<const float4*>(W_hh);
        for (int i = threadIdx.x; i < 3072; i += blockDim.x) d2[i] = s2[i];
        for (int i = threadIdx.x; i < CC * 64; i += blockDim.x) {
            int c = i / 64, j = i % 64;
            sWoT[j * CC + c] = W_out[i];
        }
        for (int i = threadIdx.x; i < 192; i += blockDim.x) {
            sbih[i] = b_ih[i];
            sbhh[i] = b_hh[i];
        }
        if (threadIdx.x < CC) sbout[threadIdx.x] = b_out[threadIdx.x];
    }
    __syncthreads();

    for (int n = blockIdx.x * NTHREADS + threadIdx.x; n < NN;
         n += NBLOCKS * NTHREADS) {

        ulonglong2 hh[16], rr[16];
        const ulonglong2* hp = reinterpret_cast<const ulonglong2*>(features + (size_t)n * 64);
        const ulonglong2* rp = reinterpret_cast<const ulonglong2*>(g_reduced + (size_t)n * 64);
#pragma unroll
        for (int q = 0; q < 16; q++) { hh[q] = hp[q]; rr[q] = rp[q]; }

        ull oacc[8];
        const ulonglong2* bo = reinterpret_cast<const ulonglong2*>(sbout);
#pragma unroll
        for (int i = 0; i < 4; i++) {
            ulonglong2 v = bo[i];
            oacc[2 * i] = v.x; oacc[2 * i + 1] = v.y;
        }

#pragma unroll 1
        for (int jq = 0; jq < 16; jq++) {
#pragma unroll
            for (int dj = 0; dj < 4; dj++) {
                int j = jq * 4 + dj;
                ull air = 0, aiz = 0, ain = 0, ahr = 0, ahz = 0, ahn = 0;
                const ulonglong2* wir = reinterpret_cast<const ulonglong2*>(sWih + (j      ) * 64);
                const ulonglong2* wiz = reinterpret_cast<const ulonglong2*>(sWih + (64  + j) * 64);
                const ulonglong2* win = reinterpret_cast<const ulonglong2*>(sWih + (128 + j) * 64);
                const ulonglong2* whr = reinterpret_cast<const ulonglong2*>(sWhh + (j      ) * 64);
                const ulonglong2* whz = reinterpret_cast<const ulonglong2*>(sWhh + (64  + j) * 64);
                const ulonglong2* whn = reinterpret_cast<const ulonglong2*>(sWhh + (128 + j) * 64);
#pragma unroll
                for (int q = 0; q < 16; q++) {
                    ulonglong2 rv = rr[q], hv = hh[q], wv;
                    wv = wir[q]; fma2(air, wv.x, rv.x); fma2(air, wv.y, rv.y);
                    wv = wiz[q]; fma2(aiz, wv.x, rv.x); fma2(aiz, wv.y, rv.y);
                    wv = win[q]; fma2(ain, wv.x, rv.x); fma2(ain, wv.y, rv.y);
                    wv = whr[q]; fma2(ahr, wv.x, hv.x); fma2(ahr, wv.y, hv.y);
                    wv = whz[q]; fma2(ahz, wv.x, hv.x); fma2(ahz, wv.y, hv.y);
                    wv = whn[q]; fma2(ahn, wv.x, hv.x); fma2(ahn, wv.y, hv.y);
                }
                float2 v;
                v = asf2(air); float ir  = v.x + v.y + sbih[j];
                v = asf2(aiz); float iz  = v.x + v.y + sbih[64 + j];
                v = asf2(ain); float inn = v.x + v.y + sbih[128 + j];
                v = asf2(ahr); float hr  = v.x + v.y + sbhh[j];
                v = asf2(ahz); float hz  = v.x + v.y + sbhh[64 + j];
                v = asf2(ahn); float hn  = v.x + v.y + sbhh[128 + j];
                float rg = fast_sigmoid(ir + hr);
                float zg = fast_sigmoid(iz + hz);
                float ng = fast_tanh(inn + rg * hn);
                float2 hjp = asf2((dj & 2) ? hh[jq].y : hh[jq].x);
                float hj = (dj & 1) ? hjp.y : hjp.x;
                float hnew = (1.f - zg) * ng + zg * hj;
                ull hn2;
                asm("mov.b64 %0, {%1, %1};" : "=l"(hn2) : "f"(hnew));
                const ulonglong2* wo = reinterpret_cast<const ulonglong2*>(sWoT + j * CC);
#pragma unroll
                for (int c = 0; c < 4; c++) {
                    ulonglong2 wv = wo[c];
                    fma2(oacc[2 * c], wv.x, hn2);
                    fma2(oacc[2 * c + 1], wv.y, hn2);
                }
            }
        }

        ulonglong2* op = reinterpret_cast<ulonglong2*>(out + (size_t)n * CC);
#pragma unroll
        for (int i = 0; i < 4; i++) {
            ulonglong2 v;
            v.x = oacc[2 * i]; v.y = oacc[2 * i + 1];
            op[i] = v;
        }
    }
}

// ---------------------------------------------------------------------------
extern "C" void kernel_launch(void* const* d_in, const int* in_sizes, int n_in,
                              void* d_out, int out_size) {
    const float* features = (const float*)d_in[0];
    const float* edge_emb = (const float*)d_in[1];
    const float* W_ih     = (const float*)d_in[2];
    const float* W_hh     = (const float*)d_in[3];
    const float* b_ih     = (const float*)d_in[4];
    const float* b_hh     = (const float*)d_in[5];
    const float* W_out    = (const float*)d_in[6];
    const float* b_out    = (const float*)d_in[7];
    const int*   etype    = (const int*)d_in[8];
    const int*   src      = (const int*)d_in[9];
    const int*   dst      = (const int*)d_in[10];
    float*       out      = (float*)d_out;

    cudaFuncSetAttribute(node_kernel, cudaFuncAttributeMaxDynamicSharedMemorySize, NODE_SMEM);

    zero_kernel<<<(NN * MSGD / 4 + 255) / 256, 256>>>();
    wprep_edge_kernel<<<128, 256>>>(edge_emb);
    hist_kernel<<<(EE + 511) / 512, 512>>>(etype);
    scatter_kernel<<<(EE + 511) / 512, 512>>>(etype, src, dst);
    edge_gemm_kernel<<<EGB, EGT>>>(features);
    node_kernel<<<NBLOCKS, NTHREADS, NODE_SMEM>>>(features, W_ih, W_hh,
                                                  b_ih, b_hh, W_out, b_out, out);
}